// round 5
// baseline (speedup 1.0000x reference)
#include <cuda_runtime.h>
#include <math.h>

#define B_DIM 128
#define N_DIM 1024
#define H_DIM 128
#define SK    128          // split-K factor for layer 1
#define KC    (N_DIM / SK) // 8: K-chunk per CTA

// Scratch (allocation-free rule: device globals).
__device__ float g_c[B_DIM * N_DIM];                    // 512 KB correlation output
__device__ float g_part[SK * B_DIM * H_DIM];            // 8 MB layer-1 partials

__device__ __forceinline__ float celu1(float v) {
    return v > 0.f ? v : expm1f(v);
}

// ---- packed fp32x2 helpers (sm_103a FFMA2) ----
__device__ __forceinline__ unsigned long long pk(float a, float b) {
    unsigned long long r;
    asm("mov.b64 %0, {%1, %2};" : "=l"(r) : "f"(a), "f"(b));
    return r;
}
__device__ __forceinline__ void ff2(unsigned long long& c,
                                    unsigned long long a, unsigned long long b) {
    asm("fma.rn.f32x2 %0, %1, %2, %0;" : "+l"(c) : "l"(a), "l"(b));
}
__device__ __forceinline__ void add2(unsigned long long& c, unsigned long long a) {
    asm("add.rn.f32x2 %0, %0, %1;" : "+l"(c) : "l"(a));
}
__device__ __forceinline__ float2 up(unsigned long long v) {
    float2 f;
    asm("mov.b64 {%0, %1}, %2;" : "=f"(f.x), "=f"(f.y) : "l"(v));
    return f;
}

// ============================================================================
// Kernel 1: circular autocorrelation per batch.
// c[b,p] = (1/N) * sum_q sum_d x[b,q,d] * x[b,(p+q)%N,d];  c[p] = c[(N-p)%N]
// 1 CTA/batch, 128 threads, 4 consecutive p per thread (p0 = 4*tid).
// Packing over adjacent p-offsets: acc01 lanes = (p0, p0+1), acc23 = (p0+2, p0+3).
//   - even window pairs (F.x,F.y)/(F.z,F.w) are aligned LDS.128 register pairs
//   - broadcast multiplier comes pre-duplicated from xb[d][q] = (v, v)
// ============================================================================
__global__ __launch_bounds__(128) void corr_kernel(const float* __restrict__ x) {
    __shared__ __align__(16) float  xs[3][2 * N_DIM];   // dense windows (dup 2x), 24KB
    __shared__ __align__(16) float2 xb[3][N_DIM];       // broadcast dup-pairs,   24KB

    const int b   = blockIdx.x;
    const int tid = threadIdx.x;
    const float* xin = x + (size_t)b * N_DIM * 3;

    for (int i = tid; i < 3 * N_DIM; i += 128) {
        float v = xin[i];
        int q = i / 3;
        int d = i - 3 * q;
        xs[d][q]         = v;
        xs[d][q + N_DIM] = v;
        xb[d][q] = make_float2(v, v);
    }
    __syncthreads();

    const int p0 = tid * 4;

    unsigned long long a01[3] = {0ull, 0ull, 0ull};
    unsigned long long a23[3] = {0ull, 0ull, 0ull};

    float4 F[3], G[3];
#pragma unroll
    for (int d = 0; d < 3; d++)
        F[d] = *(const float4*)&xs[d][p0];

    // body for one 4q step: window regs W (curr) and V (next, freshly loaded)
#define CORR_STEP(qq, W, V)                                                    \
    {                                                                          \
        _Pragma("unroll")                                                      \
        for (int d = 0; d < 3; d++)                                            \
            V[d] = *(const float4*)&xs[d][(qq) + p0 + 4];                      \
        _Pragma("unroll")                                                      \
        for (int d = 0; d < 3; d++) {                                          \
            const unsigned long long* bb =                                     \
                (const unsigned long long*)&xb[d][(qq)];                       \
            unsigned long long B0 = bb[0], B1 = bb[1], B2 = bb[2], B3 = bb[3]; \
            unsigned long long P01 = pk(W[d].x, W[d].y);                       \
            unsigned long long P12 = pk(W[d].y, W[d].z);                       \
            unsigned long long P23 = pk(W[d].z, W[d].w);                       \
            unsigned long long P34 = pk(W[d].w, V[d].x);                       \
            unsigned long long P45 = pk(V[d].x, V[d].y);                       \
            unsigned long long P56 = pk(V[d].y, V[d].z);                       \
            ff2(a01[d], B0, P01); ff2(a23[d], B0, P23);                        \
            ff2(a01[d], B1, P12); ff2(a23[d], B1, P34);                        \
            ff2(a01[d], B2, P23); ff2(a23[d], B2, P45);                        \
            ff2(a01[d], B3, P34); ff2(a23[d], B3, P56);                        \
        }                                                                      \
    }

#pragma unroll 2
    for (int q = 0; q < N_DIM; q += 8) {
        CORR_STEP(q,     F, G)   // uses F, loads G
        CORR_STEP(q + 4, G, F)   // uses G, loads F (ping-pong, no copies)
    }
#undef CORR_STEP

    const float inv = 1.0f / (float)N_DIM;
    float* cb = g_c + b * N_DIM;
    {
        unsigned long long s01 = a01[0]; add2(s01, a01[1]); add2(s01, a01[2]);
        unsigned long long s23 = a23[0]; add2(s23, a23[1]); add2(s23, a23[2]);
        float2 u = up(s01);
        float2 v = up(s23);
        float r0 = u.x * inv, r1 = u.y * inv, r2 = v.x * inv, r3 = v.y * inv;
        cb[p0 + 0] = r0;
        cb[p0 + 1] = r1;
        cb[p0 + 2] = r2;
        cb[p0 + 3] = r3;
        if (p0 > 0) cb[N_DIM - p0] = r0;
        cb[N_DIM - p0 - 1] = r1;
        cb[N_DIM - p0 - 2] = r2;
        cb[N_DIM - p0 - 3] = r3;
    }

    // p = 512 (self-mirror), warp 0 only.
    if (tid < 32) {
        float s = 0.f;
        for (int q = tid; q < N_DIM; q += 32) {
            s = fmaf(xs[0][q], xs[0][q + 512], s);
            s = fmaf(xs[1][q], xs[1][q + 512], s);
            s = fmaf(xs[2][q], xs[2][q + 512], s);
        }
#pragma unroll
        for (int off = 16; off; off >>= 1)
            s += __shfl_xor_sync(0xffffffffu, s, off);
        if (tid == 0) cb[512] = s * inv;
    }
}

// ============================================================================
// Kernel 2: layer 1 as split-K GEMM.  C[128,1024] @ W1[1024,128].
// ============================================================================
__global__ __launch_bounds__(256) void l1_kernel(const float* __restrict__ W1) {
    __shared__ __align__(16) float ct[KC][B_DIM];   // c^T chunk: [kk][m]
    __shared__ __align__(16) float wt[KC][H_DIM];   // W1 chunk:  [kk][n]

    const int sk = blockIdx.x;
    const int k0 = sk * KC;
    const int t  = threadIdx.x;

    {
        int m = t >> 1, h = t & 1;
        float4 v = *(const float4*)&g_c[(size_t)m * N_DIM + k0 + 4 * h];
        ct[4 * h + 0][m] = v.x;
        ct[4 * h + 1][m] = v.y;
        ct[4 * h + 2][m] = v.z;
        ct[4 * h + 3][m] = v.w;
    }
    {
        int kk = t >> 5, q = t & 31;
        *(float4*)&wt[kk][4 * q] =
            *(const float4*)&W1[(size_t)(k0 + kk) * H_DIM + 4 * q];
    }
    __syncthreads();

    const int m0 = (t >> 4) * 8;
    const int n0 = (t & 15) * 8;

    float4 acc[8][2];
#pragma unroll
    for (int i = 0; i < 8; i++) {
        acc[i][0] = make_float4(0.f, 0.f, 0.f, 0.f);
        acc[i][1] = make_float4(0.f, 0.f, 0.f, 0.f);
    }

#pragma unroll
    for (int kk = 0; kk < KC; kk++) {
        float4 aA = *(const float4*)&ct[kk][m0];
        float4 aB = *(const float4*)&ct[kk][m0 + 4];
        float4 b0 = *(const float4*)&wt[kk][n0];
        float4 b1 = *(const float4*)&wt[kk][n0 + 4];
        float a[8] = {aA.x, aA.y, aA.z, aA.w, aB.x, aB.y, aB.z, aB.w};
#pragma unroll
        for (int i = 0; i < 8; i++) {
            acc[i][0].x = fmaf(a[i], b0.x, acc[i][0].x);
            acc[i][0].y = fmaf(a[i], b0.y, acc[i][0].y);
            acc[i][0].z = fmaf(a[i], b0.z, acc[i][0].z);
            acc[i][0].w = fmaf(a[i], b0.w, acc[i][0].w);
            acc[i][1].x = fmaf(a[i], b1.x, acc[i][1].x);
            acc[i][1].y = fmaf(a[i], b1.y, acc[i][1].y);
            acc[i][1].z = fmaf(a[i], b1.z, acc[i][1].z);
            acc[i][1].w = fmaf(a[i], b1.w, acc[i][1].w);
        }
    }

    float* dst = g_part + (size_t)sk * B_DIM * H_DIM;
#pragma unroll
    for (int i = 0; i < 8; i++) {
        *(float4*)&dst[(size_t)(m0 + i) * H_DIM + n0]     = acc[i][0];
        *(float4*)&dst[(size_t)(m0 + i) * H_DIM + n0 + 4] = acc[i][1];
    }
}

// ============================================================================
// Kernel 3: per-batch tail (reduce partials, celu, layer2, celu, layer3).
// ============================================================================
__global__ __launch_bounds__(256) void mlp_tail_kernel(
    const float* __restrict__ b1, const float* __restrict__ W2,
    const float* __restrict__ b2, const float* __restrict__ W3,
    const float* __restrict__ b3, float* __restrict__ y)
{
    __shared__ float h1s[H_DIM];
    __shared__ float red[256];
    __shared__ float rsum[4];

    const int m = blockIdx.x;
    const int t = threadIdx.x;
    const int j    = t & 127;
    const int half = t >> 7;

    float s = 0.f;
    {
        const float* base = g_part + (size_t)half * 64 * (B_DIM * H_DIM)
                                   + (size_t)m * H_DIM + j;
#pragma unroll 16
        for (int sk = 0; sk < 64; sk++)
            s += base[(size_t)sk * (B_DIM * H_DIM)];
    }
    red[t] = s;
    __syncthreads();
    if (half == 0)
        h1s[j] = celu1(red[j] + red[j + 128] + b1[j]);
    __syncthreads();

    float a = 0.f;
    {
        const float* w = W2 + (size_t)half * 64 * H_DIM + j;
        const float* h = h1s + half * 64;
#pragma unroll 16
        for (int k = 0; k < 64; k++)
            a = fmaf(h[k], w[(size_t)k * H_DIM], a);
    }
    __syncthreads();
    red[t] = a;
    __syncthreads();

    float v = 0.f;
    if (half == 0) {
        float h2 = celu1(red[j] + red[j + 128] + b2[j]);
        v = h2 * W3[j];
#pragma unroll
        for (int off = 16; off; off >>= 1)
            v += __shfl_xor_sync(0xffffffffu, v, off);
        if ((j & 31) == 0) rsum[j >> 5] = v;
    }
    __syncthreads();
    if (t == 0)
        y[m] = rsum[0] + rsum[1] + rsum[2] + rsum[3] + b3[0];
}

extern "C" void kernel_launch(void* const* d_in, const int* in_sizes, int n_in,
                              void* d_out, int out_size) {
    const float* x  = (const float*)d_in[0];
    const float* W1 = (const float*)d_in[1];
    const float* b1 = (const float*)d_in[2];
    const float* W2 = (const float*)d_in[3];
    const float* b2 = (const float*)d_in[4];
    const float* W3 = (const float*)d_in[5];
    const float* b3 = (const float*)d_in[6];
    float* y = (float*)d_out;

    corr_kernel<<<B_DIM, 128>>>(x);
    l1_kernel<<<SK, 256>>>(W1);
    mlp_tail_kernel<<<B_DIM, 256>>>(b1, W2, b2, W3, b3, y);
}

// round 7
// speedup vs baseline: 1.0082x; 1.0082x over previous
#include <cuda_runtime.h>
#include <math.h>

#define B_DIM 128
#define N_DIM 1024
#define H_DIM 128
#define SK    128          // split-K factor for layer 1
#define KC    (N_DIM / SK) // 8: K-chunk per CTA

// Scratch (allocation-free rule: device globals).
__device__ float g_c[B_DIM * N_DIM];                    // 512 KB correlation output
__device__ float g_part[SK * B_DIM * H_DIM];            // 8 MB layer-1 partials

__device__ __forceinline__ float celu1(float v) {
    return v > 0.f ? v : expm1f(v);
}

// ---- packed fp32x2 helpers (sm_103a FFMA2) ----
__device__ __forceinline__ unsigned long long pk(float a, float b) {
    unsigned long long r;
    asm("mov.b64 %0, {%1, %2};" : "=l"(r) : "f"(a), "f"(b));
    return r;
}
__device__ __forceinline__ void ff2(unsigned long long& c,
                                    unsigned long long a, unsigned long long b) {
    asm("fma.rn.f32x2 %0, %1, %2, %0;" : "+l"(c) : "l"(a), "l"(b));
}
__device__ __forceinline__ void add2(unsigned long long& c, unsigned long long a) {
    asm("add.rn.f32x2 %0, %0, %1;" : "+l"(c) : "l"(a));
}
__device__ __forceinline__ float2 up(unsigned long long v) {
    float2 f;
    asm("mov.b64 {%0, %1}, %2;" : "=f"(f.x), "=f"(f.y) : "l"(v));
    return f;
}

// ============================================================================
// Kernel 1: circular autocorrelation per batch.
// c[b,p] = (1/N) * sum_q sum_d x[b,q,d] * x[b,(p+q)%N,d];  c[p] = c[(N-p)%N]
// 1 CTA/batch, 256 threads = 2 q-slices x 128 p-threads (2 warps/SMSP).
// Each p-thread owns 4 consecutive p (p0 = 4*(tid&127)); half h covers
// q in [h*512, h*512+512). Halves combined through SMEM at the end.
// ============================================================================
__global__ __launch_bounds__(256) void corr_kernel(const float* __restrict__ x) {
    __shared__ __align__(16) float  xs[3][2 * N_DIM];   // dense windows (dup 2x), 24KB
    __shared__ __align__(16) float2 xb[3][N_DIM];       // broadcast dup-pairs,   24KB
    __shared__ __align__(16) float4 cpart[128];         // half-1 partials,        2KB

    const int b   = blockIdx.x;
    const int tid = threadIdx.x;
    const float* xin = x + (size_t)b * N_DIM * 3;

    for (int i = tid; i < 3 * N_DIM; i += 256) {
        float v = xin[i];
        int q = i / 3;
        int d = i - 3 * q;
        xs[d][q]         = v;
        xs[d][q + N_DIM] = v;
        xb[d][q] = make_float2(v, v);
    }
    __syncthreads();

    const int pt   = tid & 127;
    const int half = tid >> 7;
    const int p0   = pt * 4;
    const int qs   = half * 512;

    unsigned long long a01[3] = {0ull, 0ull, 0ull};
    unsigned long long a23[3] = {0ull, 0ull, 0ull};

    float4 F[3], G[3];
#pragma unroll
    for (int d = 0; d < 3; d++)
        F[d] = *(const float4*)&xs[d][qs + p0];

#define CORR_STEP(qq, W, V)                                                    \
    {                                                                          \
        _Pragma("unroll")                                                      \
        for (int d = 0; d < 3; d++)                                            \
            V[d] = *(const float4*)&xs[d][(qq) + p0 + 4];                      \
        _Pragma("unroll")                                                      \
        for (int d = 0; d < 3; d++) {                                          \
            const ulonglong2* bb =                                             \
                (const ulonglong2*)&xb[d][(qq)];                               \
            ulonglong2 u0 = bb[0], u1 = bb[1];                                 \
            unsigned long long B0 = u0.x, B1 = u0.y, B2 = u1.x, B3 = u1.y;     \
            unsigned long long P01 = pk(W[d].x, W[d].y);                       \
            unsigned long long P12 = pk(W[d].y, W[d].z);                       \
            unsigned long long P23 = pk(W[d].z, W[d].w);                       \
            unsigned long long P34 = pk(W[d].w, V[d].x);                       \
            unsigned long long P45 = pk(V[d].x, V[d].y);                       \
            unsigned long long P56 = pk(V[d].y, V[d].z);                       \
            ff2(a01[d], B0, P01); ff2(a23[d], B0, P23);                        \
            ff2(a01[d], B1, P12); ff2(a23[d], B1, P34);                        \
            ff2(a01[d], B2, P23); ff2(a23[d], B2, P45);                        \
            ff2(a01[d], B3, P34); ff2(a23[d], B3, P56);                        \
        }                                                                      \
    }

#pragma unroll 2
    for (int q = qs; q < qs + 512; q += 8) {
        CORR_STEP(q,     F, G)   // uses F, loads G
        CORR_STEP(q + 4, G, F)   // uses G, loads F (ping-pong)
    }
#undef CORR_STEP

    // d-sum -> 4 floats per thread
    unsigned long long s01 = a01[0]; add2(s01, a01[1]); add2(s01, a01[2]);
    unsigned long long s23 = a23[0]; add2(s23, a23[1]); add2(s23, a23[2]);
    float2 u = up(s01);
    float2 v = up(s23);

    if (half == 1)
        cpart[pt] = make_float4(u.x, u.y, v.x, v.y);
    __syncthreads();

    const float inv = 1.0f / (float)N_DIM;
    float* cb = g_c + b * N_DIM;

    if (half == 0) {
        float4 o = cpart[pt];
        float r0 = (u.x + o.x) * inv;
        float r1 = (u.y + o.y) * inv;
        float r2 = (v.x + o.z) * inv;
        float r3 = (v.y + o.w) * inv;
        cb[p0 + 0] = r0;
        cb[p0 + 1] = r1;
        cb[p0 + 2] = r2;
        cb[p0 + 3] = r3;
        if (p0 > 0) cb[N_DIM - p0] = r0;
        cb[N_DIM - p0 - 1] = r1;
        cb[N_DIM - p0 - 2] = r2;
        cb[N_DIM - p0 - 3] = r3;
    }

    // p = 512 (self-mirror), warp 0 only (full q range; xs holds all data).
    if (tid < 32) {
        float s = 0.f;
        for (int q = tid; q < N_DIM; q += 32) {
            s = fmaf(xs[0][q], xs[0][q + 512], s);
            s = fmaf(xs[1][q], xs[1][q + 512], s);
            s = fmaf(xs[2][q], xs[2][q + 512], s);
        }
#pragma unroll
        for (int off = 16; off; off >>= 1)
            s += __shfl_xor_sync(0xffffffffu, s, off);
        if (tid == 0) cb[512] = s * inv;
    }
}

// ============================================================================
// Kernel 2: layer 1 as split-K GEMM.  C[128,1024] @ W1[1024,128].
// ============================================================================
__global__ __launch_bounds__(256) void l1_kernel(const float* __restrict__ W1) {
    __shared__ __align__(16) float ct[KC][B_DIM];   // c^T chunk: [kk][m]
    __shared__ __align__(16) float wt[KC][H_DIM];   // W1 chunk:  [kk][n]

    const int sk = blockIdx.x;
    const int k0 = sk * KC;
    const int t  = threadIdx.x;

    {
        int m = t >> 1, h = t & 1;
        float4 v = *(const float4*)&g_c[(size_t)m * N_DIM + k0 + 4 * h];
        ct[4 * h + 0][m] = v.x;
        ct[4 * h + 1][m] = v.y;
        ct[4 * h + 2][m] = v.z;
        ct[4 * h + 3][m] = v.w;
    }
    {
        int kk = t >> 5, q = t & 31;
        *(float4*)&wt[kk][4 * q] =
            *(const float4*)&W1[(size_t)(k0 + kk) * H_DIM + 4 * q];
    }
    __syncthreads();

    const int m0 = (t >> 4) * 8;
    const int n0 = (t & 15) * 8;

    float4 acc[8][2];
#pragma unroll
    for (int i = 0; i < 8; i++) {
        acc[i][0] = make_float4(0.f, 0.f, 0.f, 0.f);
        acc[i][1] = make_float4(0.f, 0.f, 0.f, 0.f);
    }

#pragma unroll
    for (int kk = 0; kk < KC; kk++) {
        float4 aA = *(const float4*)&ct[kk][m0];
        float4 aB = *(const float4*)&ct[kk][m0 + 4];
        float4 b0 = *(const float4*)&wt[kk][n0];
        float4 b1 = *(const float4*)&wt[kk][n0 + 4];
        float a[8] = {aA.x, aA.y, aA.z, aA.w, aB.x, aB.y, aB.z, aB.w};
#pragma unroll
        for (int i = 0; i < 8; i++) {
            acc[i][0].x = fmaf(a[i], b0.x, acc[i][0].x);
            acc[i][0].y = fmaf(a[i], b0.y, acc[i][0].y);
            acc[i][0].z = fmaf(a[i], b0.z, acc[i][0].z);
            acc[i][0].w = fmaf(a[i], b0.w, acc[i][0].w);
            acc[i][1].x = fmaf(a[i], b1.x, acc[i][1].x);
            acc[i][1].y = fmaf(a[i], b1.y, acc[i][1].y);
            acc[i][1].z = fmaf(a[i], b1.z, acc[i][1].z);
            acc[i][1].w = fmaf(a[i], b1.w, acc[i][1].w);
        }
    }

    float* dst = g_part + (size_t)sk * B_DIM * H_DIM;
#pragma unroll
    for (int i = 0; i < 8; i++) {
        *(float4*)&dst[(size_t)(m0 + i) * H_DIM + n0]     = acc[i][0];
        *(float4*)&dst[(size_t)(m0 + i) * H_DIM + n0 + 4] = acc[i][1];
    }
}

// ============================================================================
// Kernel 3: per-batch tail (reduce partials, celu, layer2, celu, layer3).
// ============================================================================
__global__ __launch_bounds__(256) void mlp_tail_kernel(
    const float* __restrict__ b1, const float* __restrict__ W2,
    const float* __restrict__ b2, const float* __restrict__ W3,
    const float* __restrict__ b3, float* __restrict__ y)
{
    __shared__ float h1s[H_DIM];
    __shared__ float red[256];
    __shared__ float rsum[4];

    const int m = blockIdx.x;
    const int t = threadIdx.x;
    const int j    = t & 127;
    const int half = t >> 7;

    float s = 0.f;
    {
        const float* base = g_part + (size_t)half * 64 * (B_DIM * H_DIM)
                                   + (size_t)m * H_DIM + j;
#pragma unroll 16
        for (int sk = 0; sk < 64; sk++)
            s += base[(size_t)sk * (B_DIM * H_DIM)];
    }
    red[t] = s;
    __syncthreads();
    if (half == 0)
        h1s[j] = celu1(red[j] + red[j + 128] + b1[j]);
    __syncthreads();

    float a = 0.f;
    {
        const float* w = W2 + (size_t)half * 64 * H_DIM + j;
        const float* h = h1s + half * 64;
#pragma unroll 16
        for (int k = 0; k < 64; k++)
            a = fmaf(h[k], w[(size_t)k * H_DIM], a);
    }
    __syncthreads();
    red[t] = a;
    __syncthreads();

    float v = 0.f;
    if (half == 0) {
        float h2 = celu1(red[j] + red[j + 128] + b2[j]);
        v = h2 * W3[j];
#pragma unroll
        for (int off = 16; off; off >>= 1)
            v += __shfl_xor_sync(0xffffffffu, v, off);
        if ((j & 31) == 0) rsum[j >> 5] = v;
    }
    __syncthreads();
    if (t == 0)
        y[m] = rsum[0] + rsum[1] + rsum[2] + rsum[3] + b3[0];
}

extern "C" void kernel_launch(void* const* d_in, const int* in_sizes, int n_in,
                              void* d_out, int out_size) {
    const float* x  = (const float*)d_in[0];
    const float* W1 = (const float*)d_in[1];
    const float* b1 = (const float*)d_in[2];
    const float* W2 = (const float*)d_in[3];
    const float* b2 = (const float*)d_in[4];
    const float* W3 = (const float*)d_in[5];
    const float* b3 = (const float*)d_in[6];
    float* y = (float*)d_out;

    corr_kernel<<<B_DIM, 256>>>(x);
    l1_kernel<<<SK, 256>>>(W1);
    mlp_tail_kernel<<<B_DIM, 256>>>(b1, W2, b2, W3, b3, y);
}

// round 8
// speedup vs baseline: 1.5472x; 1.5346x over previous
#include <cuda_runtime.h>
#include <math.h>

#define B_DIM 128
#define N_DIM 1024
#define H_DIM 128
#define SK    128          // split-K factor for layer 1
#define KC    (N_DIM / SK) // 8: K-chunk per CTA

// Scratch (allocation-free rule: device globals).
__device__ float g_c[B_DIM * N_DIM];                    // 512 KB correlation output
__device__ float g_part[SK * B_DIM * H_DIM];            // 8 MB layer-1 partials

__device__ __forceinline__ float celu1(float v) {
    return v > 0.f ? v : expm1f(v);
}

// ============================================================================
// Kernel 1: circular autocorrelation per batch via FFT.
//   c[b,p] = (1/N) sum_q sum_d x[b,q,d] x[b,(p+q)%N,d]
//          = (1/N) IDFT( sum_d |DFT(x_d)|^2 )[p]
// S = sum_d |X_d|^2 is real and even, so IDFT(S) = DFT(S) (both real):
// three forward complex FFTs total per batch:
//   FFT#1: z = x0 + i*x1  ->  |X0|^2+|X1|^2 = (|Z[k]|^2 + |Z[N-k]|^2)/2
//   FFT#2: x2 (+0i)       ->  |X2|^2
//   FFT#3: S              ->  c[p] = Re(FFT(S)[p]) / N^2
// Radix-2 Stockham (self-sorting), 10 stages, 512 butterflies/stage,
// 256 threads x 2 butterflies. Even #stages -> result lands back in A.
// ============================================================================
__device__ __forceinline__ void fft1024(float2* __restrict__ A,
                                        float2* __restrict__ B,
                                        const float2* __restrict__ tw,
                                        int tid) {
    float2* in  = A;
    float2* out = B;
#pragma unroll
    for (int s = 1; s <= 512; s <<= 1) {
#pragma unroll
        for (int i = 0; i < 2; i++) {
            int t    = tid + i * 256;          // butterfly id, 0..511
            int base = t & ~(s - 1);           // p*s  (p = t/s)
            float2 u = in[t];
            float2 v = in[t + 512];
            float2 w = tw[base];               // exp(-2*pi*i * base / 1024)
            float2 sum = make_float2(u.x + v.x, u.y + v.y);
            float2 d   = make_float2(u.x - v.x, u.y - v.y);
            float2 od  = make_float2(d.x * w.x - d.y * w.y,
                                     d.x * w.y + d.y * w.x);
            out[t + base]     = sum;           // index q + s*(2p)
            out[t + base + s] = od;            // index q + s*(2p+1)
        }
        __syncthreads();
        float2* tmp = in; in = out; out = tmp;
    }
}

__global__ __launch_bounds__(256) void corr_fft_kernel(const float* __restrict__ x) {
    __shared__ __align__(16) float2 A[N_DIM];     // 8KB
    __shared__ __align__(16) float2 Bb[N_DIM];    // 8KB
    __shared__ __align__(16) float2 tw[512];      // 4KB twiddles
    __shared__ __align__(16) float  S[N_DIM];     // 4KB power spectrum

    const int b   = blockIdx.x;
    const int tid = threadIdx.x;
    const float* xb = x + (size_t)b * N_DIM * 3;

    // Twiddle table: tw[j] = exp(-2*pi*i*j/1024), j = 0..511
    for (int j = tid; j < 512; j += 256) {
        float sv, cv;
        sincospif((float)j * (1.0f / 512.0f), &sv, &cv);
        tw[j] = make_float2(cv, -sv);
    }
    // FFT#1 input: z[q] = x0[q] + i*x1[q]
    for (int q = tid; q < N_DIM; q += 256)
        A[q] = make_float2(xb[3 * q + 0], xb[3 * q + 1]);
    __syncthreads();

    fft1024(A, Bb, tw, tid);   // Z in A

    // S[k] = (|Z[k]|^2 + |Z[(N-k)%N]|^2) / 2
    for (int k = tid; k < N_DIM; k += 256) {
        float2 a = A[k];
        float2 c = A[(N_DIM - k) & (N_DIM - 1)];
        S[k] = 0.5f * (a.x * a.x + a.y * a.y + c.x * c.x + c.y * c.y);
    }
    __syncthreads();

    // FFT#2 input: x2 (+ 0i)
    for (int q = tid; q < N_DIM; q += 256)
        A[q] = make_float2(xb[3 * q + 2], 0.f);
    __syncthreads();

    fft1024(A, Bb, tw, tid);   // X2 in A

    for (int k = tid; k < N_DIM; k += 256) {
        float2 a = A[k];
        S[k] += a.x * a.x + a.y * a.y;
    }
    __syncthreads();

    // FFT#3 input: S (+ 0i)
    for (int k = tid; k < N_DIM; k += 256)
        A[k] = make_float2(S[k], 0.f);
    __syncthreads();

    fft1024(A, Bb, tw, tid);   // N * r[p] in A[p].x (real, even)

    const float inv = 1.0f / ((float)N_DIM * (float)N_DIM);
    float* cb = g_c + (size_t)b * N_DIM;
    for (int p = tid; p < N_DIM; p += 256)
        cb[p] = A[p].x * inv;
}

// ============================================================================
// Kernel 2: layer 1 as split-K GEMM.  C[128,1024] @ W1[1024,128].
// ============================================================================
__global__ __launch_bounds__(256) void l1_kernel(const float* __restrict__ W1) {
    __shared__ __align__(16) float ct[KC][B_DIM];   // c^T chunk: [kk][m]
    __shared__ __align__(16) float wt[KC][H_DIM];   // W1 chunk:  [kk][n]

    const int sk = blockIdx.x;
    const int k0 = sk * KC;
    const int t  = threadIdx.x;

    {
        int m = t >> 1, h = t & 1;
        float4 v = *(const float4*)&g_c[(size_t)m * N_DIM + k0 + 4 * h];
        ct[4 * h + 0][m] = v.x;
        ct[4 * h + 1][m] = v.y;
        ct[4 * h + 2][m] = v.z;
        ct[4 * h + 3][m] = v.w;
    }
    {
        int kk = t >> 5, q = t & 31;
        *(float4*)&wt[kk][4 * q] =
            *(const float4*)&W1[(size_t)(k0 + kk) * H_DIM + 4 * q];
    }
    __syncthreads();

    const int m0 = (t >> 4) * 8;
    const int n0 = (t & 15) * 8;

    float4 acc[8][2];
#pragma unroll
    for (int i = 0; i < 8; i++) {
        acc[i][0] = make_float4(0.f, 0.f, 0.f, 0.f);
        acc[i][1] = make_float4(0.f, 0.f, 0.f, 0.f);
    }

#pragma unroll
    for (int kk = 0; kk < KC; kk++) {
        float4 aA = *(const float4*)&ct[kk][m0];
        float4 aB = *(const float4*)&ct[kk][m0 + 4];
        float4 b0 = *(const float4*)&wt[kk][n0];
        float4 b1 = *(const float4*)&wt[kk][n0 + 4];
        float a[8] = {aA.x, aA.y, aA.z, aA.w, aB.x, aB.y, aB.z, aB.w};
#pragma unroll
        for (int i = 0; i < 8; i++) {
            acc[i][0].x = fmaf(a[i], b0.x, acc[i][0].x);
            acc[i][0].y = fmaf(a[i], b0.y, acc[i][0].y);
            acc[i][0].z = fmaf(a[i], b0.z, acc[i][0].z);
            acc[i][0].w = fmaf(a[i], b0.w, acc[i][0].w);
            acc[i][1].x = fmaf(a[i], b1.x, acc[i][1].x);
            acc[i][1].y = fmaf(a[i], b1.y, acc[i][1].y);
            acc[i][1].z = fmaf(a[i], b1.z, acc[i][1].z);
            acc[i][1].w = fmaf(a[i], b1.w, acc[i][1].w);
        }
    }

    float* dst = g_part + (size_t)sk * B_DIM * H_DIM;
#pragma unroll
    for (int i = 0; i < 8; i++) {
        *(float4*)&dst[(size_t)(m0 + i) * H_DIM + n0]     = acc[i][0];
        *(float4*)&dst[(size_t)(m0 + i) * H_DIM + n0 + 4] = acc[i][1];
    }
}

// ============================================================================
// Kernel 3: per-batch tail (reduce partials, celu, layer2, celu, layer3).
// ============================================================================
__global__ __launch_bounds__(256) void mlp_tail_kernel(
    const float* __restrict__ b1, const float* __restrict__ W2,
    const float* __restrict__ b2, const float* __restrict__ W3,
    const float* __restrict__ b3, float* __restrict__ y)
{
    __shared__ float h1s[H_DIM];
    __shared__ float red[256];
    __shared__ float rsum[4];

    const int m = blockIdx.x;
    const int t = threadIdx.x;
    const int j    = t & 127;
    const int half = t >> 7;

    float s = 0.f;
    {
        const float* base = g_part + (size_t)half * 64 * (B_DIM * H_DIM)
                                   + (size_t)m * H_DIM + j;
#pragma unroll 16
        for (int sk = 0; sk < 64; sk++)
            s += base[(size_t)sk * (B_DIM * H_DIM)];
    }
    red[t] = s;
    __syncthreads();
    if (half == 0)
        h1s[j] = celu1(red[j] + red[j + 128] + b1[j]);
    __syncthreads();

    float a = 0.f;
    {
        const float* w = W2 + (size_t)half * 64 * H_DIM + j;
        const float* h = h1s + half * 64;
#pragma unroll 16
        for (int k = 0; k < 64; k++)
            a = fmaf(h[k], w[(size_t)k * H_DIM], a);
    }
    __syncthreads();
    red[t] = a;
    __syncthreads();

    float v = 0.f;
    if (half == 0) {
        float h2 = celu1(red[j] + red[j + 128] + b2[j]);
        v = h2 * W3[j];
#pragma unroll
        for (int off = 16; off; off >>= 1)
            v += __shfl_xor_sync(0xffffffffu, v, off);
        if ((j & 31) == 0) rsum[j >> 5] = v;
    }
    __syncthreads();
    if (t == 0)
        y[m] = rsum[0] + rsum[1] + rsum[2] + rsum[3] + b3[0];
}

extern "C" void kernel_launch(void* const* d_in, const int* in_sizes, int n_in,
                              void* d_out, int out_size) {
    const float* x  = (const float*)d_in[0];
    const float* W1 = (const float*)d_in[1];
    const float* b1 = (const float*)d_in[2];
    const float* W2 = (const float*)d_in[3];
    const float* b2 = (const float*)d_in[4];
    const float* W3 = (const float*)d_in[5];
    const float* b3 = (const float*)d_in[6];
    float* y = (float*)d_out;

    corr_fft_kernel<<<B_DIM, 256>>>(x);
    l1_kernel<<<SK, 256>>>(W1);
    mlp_tail_kernel<<<B_DIM, 256>>>(b1, W2, b2, W3, b3, y);
}

// round 9
// speedup vs baseline: 1.8707x; 1.2091x over previous
#include <cuda_runtime.h>
#include <math.h>

#define B_DIM 128
#define N_DIM 1024
#define H_DIM 128
#define SK    128          // split-K factor for layer 1
#define KC    (N_DIM / SK) // 8: K-chunk per CTA

// Scratch (allocation-free rule: device globals).
__device__ float g_c[B_DIM * N_DIM];                    // 512 KB correlation output
__device__ float g_part[SK * B_DIM * H_DIM];            // 8 MB layer-1 partials

__device__ __forceinline__ float celu1(float v) {
    return v > 0.f ? v : expm1f(v);
}

// Bank-conflict swizzle for FFT arrays (stride-33 rows).
#define SWZ(j) ((j) + ((j) >> 5))
#define FFT_LEN 1056   // SWZ(1023) = 1054

__device__ __forceinline__ float2 cmul(float2 a, float2 b) {
    return make_float2(a.x * b.x - a.y * b.y, a.x * b.y + a.y * b.x);
}
__device__ __forceinline__ float2 cadd(float2 a, float2 b) {
    return make_float2(a.x + b.x, a.y + b.y);
}
__device__ __forceinline__ float2 csub(float2 a, float2 b) {
    return make_float2(a.x - b.x, a.y - b.y);
}

// ============================================================================
// Radix-4 Stockham DIF stage (S = 1, 4, 16, 64, 256), 256 butterflies,
// one per thread. Output k at [q + S*(4p+k)], twiddle w^k with w = tw[p*S].
// Derivation: fusion of two radix-2 Stockham stages (s, 2s) in registers.
// ============================================================================
template <int S>
__device__ __forceinline__ void r4stage(const float2* __restrict__ in,
                                        float2* __restrict__ out,
                                        const float2* __restrict__ tw,
                                        int t) {
    const int q  = t & (S - 1);
    const int pS = t - q;                  // p*S, in [0,256)

    float2 a0 = in[SWZ(t)];
    float2 a1 = in[SWZ(t + 256)];
    float2 a2 = in[SWZ(t + 512)];
    float2 a3 = in[SWZ(t + 768)];

    float2 w1 = tw[pS];
    float2 w2 = cmul(w1, w1);
    float2 w3 = cmul(w2, w1);

    float2 s02 = cadd(a0, a2), d02 = csub(a0, a2);
    float2 s13 = cadd(a1, a3), d13 = csub(a1, a3);

    float2 b0 = cadd(s02, s13);
    float2 b2 = csub(s02, s13);
    float2 mi = make_float2(d13.y, -d13.x);      // -i * d13
    float2 b1 = cadd(d02, mi);
    float2 b3 = csub(d02, mi);

    const int o = 4 * pS + q;
    out[SWZ(o)]         = b0;
    out[SWZ(o + S)]     = cmul(b1, w1);
    out[SWZ(o + 2 * S)] = cmul(b2, w2);
    out[SWZ(o + 3 * S)] = cmul(b3, w3);
}

// 1024-pt forward FFT: input in A, output lands in B (5 stages, ping-pong).
__device__ __forceinline__ void fft1024(float2* __restrict__ A,
                                        float2* __restrict__ B,
                                        const float2* __restrict__ tw,
                                        int t) {
    r4stage<1>(A, B, tw, t);    __syncthreads();
    r4stage<4>(B, A, tw, t);    __syncthreads();
    r4stage<16>(A, B, tw, t);   __syncthreads();
    r4stage<64>(B, A, tw, t);   __syncthreads();
    r4stage<256>(A, B, tw, t);  __syncthreads();
}

// ============================================================================
// Kernel 1: circular autocorrelation per batch via FFT.
//   c[b,p] = (1/N) IDFT( sum_d |DFT(x_d)|^2 )[p];  S real+even => IDFT == DFT.
//   FFT#1: z = x0 + i*x1 -> |X0|^2+|X1|^2 = (|Z[k]|^2+|Z[N-k]|^2)/2
//   FFT#2: x2            -> += |X2|^2
//   FFT#3: S             -> c[p] = Re(.)/N^2
// ============================================================================
__global__ __launch_bounds__(256) void corr_fft_kernel(const float* __restrict__ x) {
    __shared__ __align__(16) float2 A[FFT_LEN];
    __shared__ __align__(16) float2 Bb[FFT_LEN];
    __shared__ __align__(16) float2 tw[256];
    __shared__ __align__(16) float  S[N_DIM];

    const int b   = blockIdx.x;
    const int tid = threadIdx.x;
    const float* xb = x + (size_t)b * N_DIM * 3;

    // tw[j] = exp(-2*pi*i*j/1024), j < 256
    if (tid < 256) {
        float sv, cv;
        sincospif((float)tid * (1.0f / 512.0f), &sv, &cv);
        tw[tid] = make_float2(cv, -sv);
    }
    for (int q = tid; q < N_DIM; q += 256)
        A[SWZ(q)] = make_float2(xb[3 * q + 0], xb[3 * q + 1]);
    __syncthreads();

    fft1024(A, Bb, tw, tid);   // Z in Bb

    // S[k] = (|Z[k]|^2 + |Z[N-k]|^2)/2 ; also stage FFT#2 input (x2)
    for (int k = tid; k < N_DIM; k += 256) {
        float2 a = Bb[SWZ(k)];
        float2 c = Bb[SWZ((N_DIM - k) & (N_DIM - 1))];
        S[k] = 0.5f * (a.x * a.x + a.y * a.y + c.x * c.x + c.y * c.y);
        A[SWZ(k)] = make_float2(xb[3 * k + 2], 0.f);
    }
    __syncthreads();

    fft1024(A, Bb, tw, tid);   // X2 in Bb

    // S += |X2|^2 ; stage FFT#3 input (S) in the same pass
    for (int k = tid; k < N_DIM; k += 256) {
        float2 a = Bb[SWZ(k)];
        float s = S[k] + a.x * a.x + a.y * a.y;
        A[SWZ(k)] = make_float2(s, 0.f);
    }
    __syncthreads();

    fft1024(A, Bb, tw, tid);   // N * c in Bb[.].x

    const float inv = 1.0f / ((float)N_DIM * (float)N_DIM);
    float* cb = g_c + (size_t)b * N_DIM;
    for (int p = tid; p < N_DIM; p += 256)
        cb[p] = Bb[SWZ(p)].x * inv;
}

// ============================================================================
// Kernel 2: layer 1 as split-K GEMM.  C[128,1024] @ W1[1024,128].
// ============================================================================
__global__ __launch_bounds__(256) void l1_kernel(const float* __restrict__ W1) {
    __shared__ __align__(16) float ct[KC][B_DIM];   // c^T chunk: [kk][m]
    __shared__ __align__(16) float wt[KC][H_DIM];   // W1 chunk:  [kk][n]

    const int sk = blockIdx.x;
    const int k0 = sk * KC;
    const int t  = threadIdx.x;

    {
        int m = t >> 1, h = t & 1;
        float4 v = *(const float4*)&g_c[(size_t)m * N_DIM + k0 + 4 * h];
        ct[4 * h + 0][m] = v.x;
        ct[4 * h + 1][m] = v.y;
        ct[4 * h + 2][m] = v.z;
        ct[4 * h + 3][m] = v.w;
    }
    {
        int kk = t >> 5, q = t & 31;
        *(float4*)&wt[kk][4 * q] =
            *(const float4*)&W1[(size_t)(k0 + kk) * H_DIM + 4 * q];
    }
    __syncthreads();

    const int m0 = (t >> 4) * 8;
    const int n0 = (t & 15) * 8;

    float4 acc[8][2];
#pragma unroll
    for (int i = 0; i < 8; i++) {
        acc[i][0] = make_float4(0.f, 0.f, 0.f, 0.f);
        acc[i][1] = make_float4(0.f, 0.f, 0.f, 0.f);
    }

#pragma unroll
    for (int kk = 0; kk < KC; kk++) {
        float4 aA = *(const float4*)&ct[kk][m0];
        float4 aB = *(const float4*)&ct[kk][m0 + 4];
        float4 b0 = *(const float4*)&wt[kk][n0];
        float4 b1 = *(const float4*)&wt[kk][n0 + 4];
        float a[8] = {aA.x, aA.y, aA.z, aA.w, aB.x, aB.y, aB.z, aB.w};
#pragma unroll
        for (int i = 0; i < 8; i++) {
            acc[i][0].x = fmaf(a[i], b0.x, acc[i][0].x);
            acc[i][0].y = fmaf(a[i], b0.y, acc[i][0].y);
            acc[i][0].z = fmaf(a[i], b0.z, acc[i][0].z);
            acc[i][0].w = fmaf(a[i], b0.w, acc[i][0].w);
            acc[i][1].x = fmaf(a[i], b1.x, acc[i][1].x);
            acc[i][1].y = fmaf(a[i], b1.y, acc[i][1].y);
            acc[i][1].z = fmaf(a[i], b1.z, acc[i][1].z);
            acc[i][1].w = fmaf(a[i], b1.w, acc[i][1].w);
        }
    }

    float* dst = g_part + (size_t)sk * B_DIM * H_DIM;
#pragma unroll
    for (int i = 0; i < 8; i++) {
        *(float4*)&dst[(size_t)(m0 + i) * H_DIM + n0]     = acc[i][0];
        *(float4*)&dst[(size_t)(m0 + i) * H_DIM + n0 + 4] = acc[i][1];
    }
}

// ============================================================================
// Kernel 3: per-batch tail (reduce partials, celu, layer2, celu, layer3).
// ============================================================================
__global__ __launch_bounds__(256) void mlp_tail_kernel(
    const float* __restrict__ b1, const float* __restrict__ W2,
    const float* __restrict__ b2, const float* __restrict__ W3,
    const float* __restrict__ b3, float* __restrict__ y)
{
    __shared__ float h1s[H_DIM];
    __shared__ float red[256];
    __shared__ float rsum[4];

    const int m = blockIdx.x;
    const int t = threadIdx.x;
    const int j    = t & 127;
    const int half = t >> 7;

    float s = 0.f;
    {
        const float* base = g_part + (size_t)half * 64 * (B_DIM * H_DIM)
                                   + (size_t)m * H_DIM + j;
#pragma unroll 16
        for (int sk = 0; sk < 64; sk++)
            s += base[(size_t)sk * (B_DIM * H_DIM)];
    }
    red[t] = s;
    __syncthreads();
    if (half == 0)
        h1s[j] = celu1(red[j] + red[j + 128] + b1[j]);
    __syncthreads();

    float a = 0.f;
    {
        const float* w = W2 + (size_t)half * 64 * H_DIM + j;
        const float* h = h1s + half * 64;
#pragma unroll 16
        for (int k = 0; k < 64; k++)
            a = fmaf(h[k], w[(size_t)k * H_DIM], a);
    }
    __syncthreads();
    red[t] = a;
    __syncthreads();

    float v = 0.f;
    if (half == 0) {
        float h2 = celu1(red[j] + red[j + 128] + b2[j]);
        v = h2 * W3[j];
#pragma unroll
        for (int off = 16; off; off >>= 1)
            v += __shfl_xor_sync(0xffffffffu, v, off);
        if ((j & 31) == 0) rsum[j >> 5] = v;
    }
    __syncthreads();
    if (t == 0)
        y[m] = rsum[0] + rsum[1] + rsum[2] + rsum[3] + b3[0];
}

extern "C" void kernel_launch(void* const* d_in, const int* in_sizes, int n_in,
                              void* d_out, int out_size) {
    const float* x  = (const float*)d_in[0];
    const float* W1 = (const float*)d_in[1];
    const float* b1 = (const float*)d_in[2];
    const float* W2 = (const float*)d_in[3];
    const float* b2 = (const float*)d_in[4];
    const float* W3 = (const float*)d_in[5];
    const float* b3 = (const float*)d_in[6];
    float* y = (float*)d_out;

    corr_fft_kernel<<<B_DIM, 256>>>(x);
    l1_kernel<<<SK, 256>>>(W1);
    mlp_tail_kernel<<<B_DIM, 256>>>(b1, W2, b2, W3, b3, y);
}